// round 17
// baseline (speedup 1.0000x reference)
#include <cuda_runtime.h>
#include <math.h>
#include <stdint.h>

#define BSZ  4096
#define KSEL 200
#define CLO  0.10f
#define CHI  0.22f
#define CAP  768

// ---- scratch (__device__ globals; no allocations allowed) ----
__device__ float  g_Ft[(size_t)32 * 128 * 128];  // k-major tiles: [block][k][row], 2 MB
__device__ float4 g_part[(size_t)BSZ * 32];      // per (row, tilecol): psum, e_pos, e_hi, packed
__device__ float  g_cand[(size_t)BSZ * CAP];     // negative values in (CLO, CHI]
__device__ int    g_ccnt[BSZ];                   // zero-init; row_kernel re-zeroes after use
__device__ float  g_perrow[BSZ];
__device__ float  g_validf[BSZ];
__device__ int    g_done;                        // zero-init; last block resets

// packed f32x2 helpers (plain PTX, valid on compute_103)
__device__ __forceinline__ void fma2(unsigned long long& d,
                                     unsigned long long a,
                                     unsigned long long b) {
    asm("fma.rn.f32x2 %0, %1, %2, %0;" : "+l"(d) : "l"(a), "l"(b));
}
__device__ __forceinline__ unsigned long long splat2(float x) {
    unsigned long long r;
    asm("mov.b64 %0, {%1, %1};" : "=l"(r) : "f"(x));
    return r;
}
__device__ __forceinline__ void cp16(uint32_t dst_smem, const void* src) {
    asm volatile("cp.async.cg.shared.global [%0], [%1], 16;"
                 :: "r"(dst_smem), "l"(src) : "memory");
}

// ===========================================================================
// Transpose F (row-major [4096][128]) into k-major 128-row blocks g_Ft.
// ===========================================================================
__global__ void transpose_k(const float* __restrict__ F) {
    __shared__ float t[32][33];
    const int b  = blockIdx.z;
    const int rt = blockIdx.x * 32, kt = blockIdx.y * 32;
    const int tx = threadIdx.x, ty = threadIdx.y;
#pragma unroll
    for (int i = 0; i < 32; i += 8)
        t[ty + i][tx] = F[(size_t)(b * 128 + rt + ty + i) * 128 + kt + tx];
    __syncthreads();
#pragma unroll
    for (int i = 0; i < 32; i += 8)
        g_Ft[(size_t)b * 16384 + (kt + ty + i) * 128 + rt + tx] = t[tx][ty + i];
}

// ===========================================================================
// Fused GEMM + statistics epilogue. 128x128 tiles, triangular grid (528).
// cp.async 2-stage pipeline over 4 chunks of K=32.
// Epilogue uses ballot-aggregated atomics (direct) and single-atomic
// two-pass appends (mirror).
// ===========================================================================
#define KCH 32
#define STG_F 8448                               // floats per stage (A 4224 + B 4224)

__global__ __launch_bounds__(256, 2) void gemm_stats(const int* __restrict__ labels) {
    extern __shared__ float smem[];
    __shared__ int labsh[256];

    int lin = blockIdx.x;
    int by = 0;
    while (lin >= 32 - by) { lin -= 32 - by; by++; }
    int bx = by + lin;
    const int bi = by * 128, bj = bx * 128;

    const int tid = threadIdx.x;
    const int tx = tid & 15, ty = tid >> 4;
    const int lane = tid & 31;

    if (tid < 128) labsh[tid] = labels[bi + tid];
    else           labsh[tid] = labels[bj + tid - 128];

    unsigned long long acc2[4][8];
#pragma unroll
    for (int p = 0; p < 4; p++)
#pragma unroll
        for (int c = 0; c < 8; c++) acc2[p][c] = 0ULL;

    const float* srcA = g_Ft + (size_t)by * 16384;
    const float* srcB = g_Ft + (size_t)bx * 16384;
    const uint32_t sbase = (uint32_t)__cvta_generic_to_shared(smem);

    auto issue = [&](int c, int s) {
        uint32_t stg = sbase + (uint32_t)(s * STG_F * 4);
#pragma unroll
        for (int i = 0; i < 4; i++) {
            int id = tid + i * 256;
            int k = id >> 5, rq = id & 31;
            uint32_t off = (uint32_t)((k * 132 + rq * 4) * 4);
            const float* sA = srcA + (c * KCH + k) * 128 + rq * 4;
            const float* sB = srcB + (c * KCH + k) * 128 + rq * 4;
            cp16(stg + off, sA);
            cp16(stg + 4224 * 4 + off, sB);
        }
        asm volatile("cp.async.commit_group;" ::: "memory");
    };

    issue(0, 0);
#pragma unroll 1
    for (int c = 0; c < 4; c++) {
        if (c < 3) issue(c + 1, (c + 1) & 1);
        if (c < 3) asm volatile("cp.async.wait_group 1;" ::: "memory");
        else       asm volatile("cp.async.wait_group 0;" ::: "memory");
        __syncthreads();
        const float4* As4 = reinterpret_cast<const float4*>(smem + (c & 1) * STG_F);
        const float4* Bs4 = As4 + 1056;
#pragma unroll 8
        for (int k = 0; k < KCH; k++) {
            float4 av0 = As4[k * 33 + ty];
            float4 av1 = As4[k * 33 + 16 + ty];
            float4 bv0 = Bs4[k * 33 + tx];
            float4 bv1 = Bs4[k * 33 + 16 + tx];
            unsigned long long A0 = reinterpret_cast<const ulonglong2*>(&av0)->x;
            unsigned long long A1 = reinterpret_cast<const ulonglong2*>(&av0)->y;
            unsigned long long A2 = reinterpret_cast<const ulonglong2*>(&av1)->x;
            unsigned long long A3 = reinterpret_cast<const ulonglong2*>(&av1)->y;
            unsigned long long B[8];
            B[0] = splat2(bv0.x); B[1] = splat2(bv0.y);
            B[2] = splat2(bv0.z); B[3] = splat2(bv0.w);
            B[4] = splat2(bv1.x); B[5] = splat2(bv1.y);
            B[6] = splat2(bv1.z); B[7] = splat2(bv1.w);
#pragma unroll
            for (int cc = 0; cc < 8; cc++) {
                fma2(acc2[0][cc], A0, B[cc]);
                fma2(acc2[1][cc], A1, B[cc]);
                fma2(acc2[2][cc], A2, B[cc]);
                fma2(acc2[3][cc], A3, B[cc]);
            }
        }
        __syncthreads();
    }

    auto accf = [&](int p, int c, int half) -> float {
        float2 f = *reinterpret_cast<float2*>(&acc2[p][c]);
        return half ? f.y : f.x;
    };
    auto rowOf = [&](int p, int h) -> int {
        return (p < 2) ? (ty * 4 + 2 * p + h) : (64 + ty * 4 + 2 * (p - 2) + h);
    };
    auto colOf = [&](int c) -> int {
        return (c < 4) ? (tx * 4 + c) : (64 + tx * 4 + (c - 4));
    };

    const bool diag = (bx == by);

    // ---- direct role: rows in block by, tilecol bx (unique writer) ----
#pragma unroll
    for (int p = 0; p < 4; p++)
#pragma unroll
        for (int h = 0; h < 2; h++) {
            int r = rowOf(p, h);
            int labr = labsh[r];
            float ps = 0.0f, ep = 0.0f, eh = 0.0f;
            int pc = 0, ch = 0;
#pragma unroll
            for (int c = 0; c < 8; c++) {
                float x = accf(p, c, h);
                int cloc = colOf(c);
                if (labsh[128 + cloc] == labr) {
                    if (!(diag && cloc == r)) {
                        ps += x; pc++;
                        ep += __expf(10.0f * (x - 1.0f));
                    }
                } else if (x > CHI) {
                    eh += __expf(10.0f * (x - 1.0f)); ch++;
                }
            }
            // candidate appends: half-warp ballot aggregation, 1 atomic/group
#pragma unroll
            for (int c = 0; c < 8; c++) {
                float x = accf(p, c, h);
                int cloc = colOf(c);
                bool win = (labsh[128 + cloc] != labr) && (x > CLO) && (x <= CHI);
                unsigned bal = __ballot_sync(0xFFFFFFFFu, win);
                unsigned halfm = (bal >> (lane & 16)) & 0xFFFFu;
                int cnt = __popc(halfm);
                int pre = __popc(halfm & ((1u << (lane & 15)) - 1u));
                int bb = 0;
                if ((lane & 15) == 0 && cnt)
                    bb = atomicAdd(&g_ccnt[bi + r], cnt);
                bb = __shfl_sync(0xFFFFFFFFu, bb, lane & 16);
                if (win) {
                    int id = bb + pre;
                    if (id < CAP) g_cand[(size_t)(bi + r) * CAP + id] = x;
                }
            }
            int pk = pc | (ch << 16);
#pragma unroll
            for (int off = 8; off; off >>= 1) {
                ps += __shfl_down_sync(0xFFFFFFFFu, ps, off, 16);
                ep += __shfl_down_sync(0xFFFFFFFFu, ep, off, 16);
                eh += __shfl_down_sync(0xFFFFFFFFu, eh, off, 16);
                pk += __shfl_down_sync(0xFFFFFFFFu, pk, off, 16);
            }
            if (tx == 0)
                g_part[(size_t)(bi + r) * 32 + bx] =
                    make_float4(ps, ep, eh, __int_as_float(pk));
        }

    // ---- mirror role: rows in block bx, tilecol by (off-diagonal only) ----
    if (!diag) {
        float2* sh2 = reinterpret_cast<float2*>(smem);
#pragma unroll
        for (int c = 0; c < 8; c++) {
            int cloc = colOf(c);
            int labc = labsh[128 + cloc];
            float ps = 0.0f, ep = 0.0f;
#pragma unroll
            for (int p = 0; p < 4; p++)
#pragma unroll
                for (int h = 0; h < 2; h++) {
                    int r = rowOf(p, h);
                    float x = accf(p, c, h);
                    if (labsh[r] == labc) { ps += x; ep += __expf(10.0f * (x - 1.0f)); }
                }
            sh2[ty * 132 + cloc] = make_float2(ps, ep);
        }
        __syncthreads();
        float mps = 0.0f, mep = 0.0f;
        if (tid < 128)
#pragma unroll
            for (int t = 0; t < 16; t++) {
                float2 v = sh2[t * 132 + tid];
                mps += v.x; mep += v.y;
            }
        __syncthreads();
#pragma unroll
        for (int c = 0; c < 8; c++) {
            int cloc = colOf(c);
            int labc = labsh[128 + cloc];
            float eh = 0.0f;
            int pc = 0, ch = 0, nwin = 0;
#pragma unroll
            for (int p = 0; p < 4; p++)
#pragma unroll
                for (int h = 0; h < 2; h++) {
                    int r = rowOf(p, h);
                    float x = accf(p, c, h);
                    if (labsh[r] == labc) pc++;
                    else if (x > CHI) { eh += __expf(10.0f * (x - 1.0f)); ch++; }
                    else if (x > CLO) nwin++;
                }
            if (nwin) {                      // ONE atomic per (thread, col)
                int basei = atomicAdd(&g_ccnt[bj + cloc], nwin);
                int o = 0;
#pragma unroll
                for (int p = 0; p < 4; p++)
#pragma unroll
                    for (int h = 0; h < 2; h++) {
                        int r = rowOf(p, h);
                        float x = accf(p, c, h);
                        if (labsh[r] != labc && x > CLO && x <= CHI) {
                            int id = basei + o;
                            if (id < CAP) g_cand[(size_t)(bj + cloc) * CAP + id] = x;
                            o++;
                        }
                    }
            }
            sh2[ty * 132 + cloc] = make_float2(eh, (float)(pc | (ch << 16)));
        }
        __syncthreads();
        if (tid < 128) {
            float meh = 0.0f, mpk = 0.0f;
#pragma unroll
            for (int t = 0; t < 16; t++) {
                float2 v = sh2[t * 132 + tid];
                meh += v.x; mpk += v.y;
            }
            g_part[(size_t)(bj + tid) * 32 + by] =
                make_float4(mps, mep, meh, __int_as_float((int)mpk));
        }
    }
}

// ===========================================================================
// Row kernel: one warp per row (8 rows/block, 512 blocks). Candidates staged
// in smem; fine-threshold bracket; ballot-compaction; O(bracket^2) smem rank.
// Exact slow fallback. Last block does the deterministic final reduction.
// ===========================================================================
__global__ __launch_bounds__(256) void row_kernel(const float* __restrict__ F,
                                                  const int* __restrict__ labels,
                                                  float* __restrict__ out) {
    __shared__ float s_cand[8][CAP];
    __shared__ float s_list[8][256];
    __shared__ int   s_lc[8];
    __shared__ float sp[256], sv[256];
    __shared__ int   lastf;

    const unsigned FULL = 0xFFFFFFFFu;
    const int w = threadIdx.x >> 5, lane = threadIdx.x & 31;
    const int row = blockIdx.x * 8 + w;

    float4 p4 = g_part[(size_t)row * 32 + lane];
    float psum = p4.x, epos = p4.y, ehi = p4.z;
    int pk = __float_as_int(p4.w);
#pragma unroll
    for (int off = 16; off; off >>= 1) {
        psum += __shfl_xor_sync(FULL, psum, off);
        epos += __shfl_xor_sync(FULL, epos, off);
        ehi  += __shfl_xor_sync(FULL, ehi,  off);
        pk   += __shfl_xor_sync(FULL, pk,   off);
    }
    const int pcnt = pk & 0xFFFF, chi = pk >> 16;
    const int labi = labels[row];
    const bool active = (labi > 0) && (pcnt > 0);

    if (!active) {
        if (lane == 0) { g_perrow[row] = 0.0f; g_validf[row] = 0.0f; }
    } else {
        const int negcnt = BSZ - 1 - pcnt;
        const int ccnt = g_ccnt[row];
        const float* base = g_cand + (size_t)row * CAP;

        bool slow = (negcnt <= KSEL) || (ccnt > CAP) ||
                    !(chi < KSEL && KSEL <= chi + ccnt);
        float E = 0.0f;

        if (!slow) {
            // stage candidates into smem once
            for (int u = lane; u < ccnt; u += 32) s_cand[w][u] = base[u];
            __syncwarp();

            const int kneed = KSEL - chi;
            int ct[11];
#pragma unroll
            for (int j = 0; j < 11; j++) ct[j] = 0;
            for (int u = lane; u < ccnt; u += 32) {
                float x = s_cand[w][u];
#pragma unroll
                for (int j = 0; j < 11; j++)
                    ct[j] += x > (0.11f + 0.01f * (float)j);
            }
#pragma unroll
            for (int j = 0; j < 11; j++)
#pragma unroll
                for (int off = 16; off; off >>= 1)
                    ct[j] += __shfl_xor_sync(FULL, ct[j], off);

            float blo = 0.21f, bhi = CHI;
            int cAwin = 0;
#pragma unroll
            for (int j = 10; j >= 0; j--)
                if (ct[j] < kneed) {
                    bhi = 0.11f + 0.01f * (float)j;
                    blo = (j == 0) ? CLO : (0.11f + 0.01f * (float)(j - 1));
                    cAwin = ct[j];
                }
            const int cAbove = chi + cAwin;

            int nlist = 0;
            int iters = (ccnt + 31) & ~31;
            for (int ub = 0; ub < iters; ub += 32) {
                int u = ub + lane;
                float x = (u < ccnt) ? s_cand[w][u] : -1.0f;
                bool pred = (x > blo) && (x <= bhi);
                unsigned bal = __ballot_sync(FULL, pred);
                int pos = nlist + __popc(bal & ((1u << lane) - 1u));
                if (pred && pos < 256) s_list[w][pos] = x;
                nlist += __popc(bal);
            }
            if (nlist > 256) slow = true;
            __syncwarp();

            if (!slow) {
                float T = 0.0f; int gtT = 0, have = 0;
                for (int t = lane; t < nlist; t += 32) {
                    float x = s_list[w][t];
                    int g = 0, e = 0;
                    for (int u = 0; u < nlist; u++) {
                        float y = s_list[w][u];
                        g += y > x; e += y == x;
                    }
                    int tg = cAbove + g;
                    if (tg < KSEL && KSEL <= tg + e) { T = x; gtT = tg; have = 1; }
                }
                unsigned bal = __ballot_sync(FULL, have);
                if (!bal) slow = true;
                else {
                    int src = __ffs(bal) - 1;
                    T   = __shfl_sync(FULL, T, src);
                    gtT = __shfl_sync(FULL, gtT, src);
                    const int ties = KSEL - gtT;
                    double ns = 0.0;
                    for (int u = lane; u < ccnt; u += 32) {
                        float x = s_cand[w][u];
                        if (x > T) ns += (double)__expf(10.0f * (x - 1.0f));
                    }
#pragma unroll
                    for (int off = 16; off; off >>= 1)
                        ns += __shfl_xor_sync(FULL, ns, off);
                    E = epos + ehi + (float)ns + (float)ties * __expf(10.0f * (T - 1.0f));
                }
            }
        }

        if (slow) {
            // exact fallback: recompute row dots from F (row vector via s_cand space)
            float4* fi4 = reinterpret_cast<float4*>(s_cand[w]);
            const float4* F4 = reinterpret_cast<const float4*>(F);
            fi4[lane] = F4[(size_t)row * 32 + lane];
            __syncwarp();
            auto dotj = [&](int j) -> float {
                float a = 0.0f;
                const float4* fj = F4 + (size_t)j * 32;
#pragma unroll 8
                for (int q = 0; q < 32; q++) {
                    float4 av = fi4[q]; float4 bv = fj[q];
                    a += av.x * bv.x + av.y * bv.y + av.z * bv.z + av.w * bv.w;
                }
                return a;
            };

            if (negcnt <= KSEL) {
                double nsa = 0.0;
                for (int j = lane; j < BSZ; j += 32)
                    if (labels[j] != labi)
                        nsa += (double)__expf(10.0f * (dotj(j) - 1.0f));
#pragma unroll
                for (int off = 16; off; off >>= 1)
                    nsa += __shfl_xor_sync(FULL, nsa, off);
                E = epos + (float)nsa;
            } else {
                float blo = -1.01f, bhi = 1.01f;
                int cLo = negcnt, cHi = 0;
                for (int round = 0; round < 12 && (cLo - cHi) > 48; round++) {
                    float tt[8];
#pragma unroll
                    for (int k = 0; k < 8; k++)
                        tt[k] = blo + (bhi - blo) * (float)(k + 1) * (1.0f / 9.0f);
                    int cc[8] = {0, 0, 0, 0, 0, 0, 0, 0};
                    for (int j = lane; j < BSZ; j += 32)
                        if (labels[j] != labi) {
                            float x = dotj(j);
#pragma unroll
                            for (int k = 0; k < 8; k++) cc[k] += x > tt[k];
                        }
#pragma unroll
                    for (int k = 0; k < 8; k++)
#pragma unroll
                        for (int off = 16; off; off >>= 1)
                            cc[k] += __shfl_xor_sync(FULL, cc[k], off);
                    int js = 8;
#pragma unroll
                    for (int k = 7; k >= 0; k--) if (cc[k] < KSEL) js = k;
                    if (js == 8)      { blo = tt[7]; cLo = cc[7]; }
                    else if (js == 0) { bhi = tt[0]; cHi = cc[0]; }
                    else { blo = tt[js - 1]; cLo = cc[js - 1];
                           bhi = tt[js];     cHi = cc[js]; }
                }
                if (lane == 0) s_lc[w] = 0;
                __syncwarp();
                double nsh = 0.0;
                for (int j = lane; j < BSZ; j += 32)
                    if (labels[j] != labi) {
                        float x = dotj(j);
                        if (x > bhi) nsh += (double)__expf(10.0f * (x - 1.0f));
                        else if (x > blo) {
                            int id = atomicAdd(&s_lc[w], 1);
                            if (id < 256) s_list[w][id] = x;
                        }
                    }
                __syncwarp();
#pragma unroll
                for (int off = 16; off; off >>= 1)
                    nsh += __shfl_xor_sync(FULL, nsh, off);
                int nc = min(s_lc[w], 256);
                float Tf = 0.0f; int gf = 0, hv = 0;
                for (int t2 = lane; t2 < nc; t2 += 32) {
                    float x = s_list[w][t2];
                    int g = 0, e = 0;
                    for (int u = 0; u < nc; u++) {
                        float y = s_list[w][u];
                        g += y > x; e += y == x;
                    }
                    if (cHi + g < KSEL && KSEL <= cHi + g + e) { Tf = x; gf = g; hv = 1; }
                }
                unsigned bal = __ballot_sync(FULL, hv);
                int src = (bal ? __ffs(bal) - 1 : 0);
                Tf = __shfl_sync(FULL, Tf, src);
                gf = __shfl_sync(FULL, gf, src);
                const int ties = KSEL - cHi - gf;
                double nsb = 0.0;
                for (int t2 = lane; t2 < nc; t2 += 32) {
                    float x = s_list[w][t2];
                    if (x > Tf) nsb += (double)__expf(10.0f * (x - 1.0f));
                }
#pragma unroll
                for (int off = 16; off; off >>= 1)
                    nsb += __shfl_xor_sync(FULL, nsb, off);
                E = epos + (float)nsh + (float)nsb + (float)ties * __expf(10.0f * (Tf - 1.0f));
            }
        }

        if (lane == 0) {
            float pr = -2.0f * (10.0f * (psum / (float)pcnt - 1.0f) - logf(E));
            g_perrow[row] = pr;
            g_validf[row] = 1.0f;
        }
    }

    // reset candidate counter for the next (graph-replayed) launch
    if (lane == 0) g_ccnt[row] = 0;

    // ---- merged finalize: last block does the deterministic reduction ----
    __threadfence();
    __syncthreads();
    if (threadIdx.x == 0)
        lastf = (atomicAdd(&g_done, 1) == (int)gridDim.x - 1);
    __syncthreads();
    if (lastf) {
        int tid = threadIdx.x;
        float ps = 0.0f, vs = 0.0f;
        for (int j = tid; j < BSZ; j += 256) { ps += g_perrow[j]; vs += g_validf[j]; }
        sp[tid] = ps; sv[tid] = vs;
        __syncthreads();
#pragma unroll
        for (int o = 128; o; o >>= 1) {
            if (tid < o) { sp[tid] += sp[tid + o]; sv[tid] += sv[tid + o]; }
            __syncthreads();
        }
        if (tid == 0) {
            out[0] = sp[0] / sv[0];
            g_done = 0;
        }
    }
}

// ===========================================================================
extern "C" void kernel_launch(void* const* d_in, const int* in_sizes, int n_in,
                              void* d_out, int out_size) {
    (void)in_sizes; (void)n_in; (void)out_size;
    const float* F      = (const float*)d_in[0];
    const int*   labels = (const int*)d_in[1];
    float*       out    = (float*)d_out;

    cudaFuncSetAttribute(gemm_stats, cudaFuncAttributeMaxDynamicSharedMemorySize,
                         2 * STG_F * 4);

    transpose_k<<<dim3(4, 4, 32), dim3(32, 8)>>>(F);
    gemm_stats<<<528, 256, 2 * STG_F * 4>>>(labels);
    row_kernel<<<512, 256>>>(F, labels, out);
}